// round 7
// baseline (speedup 1.0000x reference)
#include <cuda_runtime.h>
#include <math.h>

#define N_CELLS 8192
#define HID 128
#define IN_DIM 64
#define OUT_DIM 64
#define NFAC 8
#define FS 1024
#define TOPK 8

__device__ float g_signal[HID];
__device__ float g_dists[N_CELLS];
__device__ float g_fsum[NFAC * HID];

// ---------------------------------------------------------------------------
// K1: signal = x @ in_w.T + in_b ; also zero the faction-sum accumulator
// ---------------------------------------------------------------------------
__global__ void k_signal(const float* __restrict__ x,
                         const float* __restrict__ in_w,
                         const float* __restrict__ in_b) {
    int tid = threadIdx.x;
    for (int i = tid; i < NFAC * HID; i += blockDim.x) g_fsum[i] = 0.f;
    if (tid < HID) {
        float acc = in_b[tid];
        const float* wrow = in_w + tid * IN_DIM;
#pragma unroll
        for (int i = 0; i < IN_DIM; ++i) acc += x[i] * wrow[i];
        g_signal[tid] = acc;
    }
}

// ---------------------------------------------------------------------------
// K2: per-row squared distance to signal + per-faction prototype sums
// warp-per-row; 8 rows per block; 1024 blocks (128 blocks per faction;
// faction = blockIdx.x >> 7 since 8 rows/block and 1024 rows/faction)
// ---------------------------------------------------------------------------
__global__ void k_dists(const float* __restrict__ proto) {
    __shared__ float ssig[HID];
    __shared__ float sfs[HID];
    int tid = threadIdx.x;
    if (tid < HID) { ssig[tid] = g_signal[tid]; sfs[tid] = 0.f; }
    __syncthreads();

    int wid = tid >> 5, lane = tid & 31;
    int row = blockIdx.x * 8 + wid;
    const float4* p4 = (const float4*)(proto + (size_t)row * HID);
    float4 a = p4[lane];
    int d0 = lane * 4;
    float dx = a.x - ssig[d0 + 0];
    float dy = a.y - ssig[d0 + 1];
    float dz = a.z - ssig[d0 + 2];
    float dw = a.w - ssig[d0 + 3];
    float s = dx * dx + dy * dy + dz * dz + dw * dw;

    atomicAdd(&sfs[d0 + 0], a.x);
    atomicAdd(&sfs[d0 + 1], a.y);
    atomicAdd(&sfs[d0 + 2], a.z);
    atomicAdd(&sfs[d0 + 3], a.w);

#pragma unroll
    for (int off = 16; off; off >>= 1) s += __shfl_down_sync(0xffffffffu, s, off);
    if (lane == 0) g_dists[row] = s;

    __syncthreads();
    if (tid < HID) atomicAdd(&g_fsum[(blockIdx.x >> 7) * HID + tid], sfs[tid]);
}

// ---------------------------------------------------------------------------
// K3: everything else in one block of 1024 threads
// ---------------------------------------------------------------------------
__global__ void __launch_bounds__(1024, 1)
k_main(const float* __restrict__ proto,
       const float* __restrict__ edges,
       const float* __restrict__ eages,
       const int* __restrict__ stepp,
       const float* __restrict__ out_w, const float* __restrict__ out_b,
       const float* __restrict__ ea_w1, const float* __restrict__ ea_b1,
       const float* __restrict__ ea_w2, const float* __restrict__ ea_b2,
       const float* __restrict__ eg_w1, const float* __restrict__ eg_b1,
       const float* __restrict__ eg_w2, const float* __restrict__ eg_b2,
       float* __restrict__ out) {
    __shared__ float ssig[HID];
    __shared__ float dsum[NFAC][HID];
    __shared__ int   cnt[NFAC];
    __shared__ int   topi[TOPK];
    __shared__ float topd[TOPK];
    __shared__ float w8[TOPK];
    __shared__ float fmean[NFAC][HID];
    __shared__ float gmean[HID];
    __shared__ float p1s[HID], p2s[HID];
    __shared__ float win[HID];
    __shared__ float comb[HID];
    __shared__ float h1[HID], h2[HID];
    __shared__ float rd[32];
    __shared__ int   ri[32];
    __shared__ unsigned char nmask[N_CELLS];
    __shared__ float s_epsw, s_epsn;
    __shared__ int   s_b1, s_b2, s_step;

    int tid = threadIdx.x;
    int lane = tid & 31, wid = tid >> 5;

    if (tid < HID) ssig[tid] = g_signal[tid];
    {
        float* dz = &dsum[0][0];
        for (int i = tid; i < NFAC * HID; i += blockDim.x) dz[i] = 0.f;
    }
    if (tid < NFAC) cnt[tid] = 0;
    __syncthreads();

    // ---- top-8 selection: 8 sequential argmins, ties -> lower index.
    // After pass 0 resolves bmu1, prefetch its 64KB edge/age row into
    // registers; the remaining 7 passes hide the DRAM round trip.
    float pe[8], pa[8];
    for (int k = 0; k < TOPK; ++k) {
        float best = 3.4e38f;
        int bi = N_CELLS;
        for (int j = tid; j < N_CELLS; j += 1024) {
            bool skip = false;
#pragma unroll
            for (int t = 0; t < TOPK; ++t)
                if (t < k && topi[t] == j) skip = true;
            if (!skip) {
                float d = g_dists[j];
                if (d < best || (d == best && j < bi)) { best = d; bi = j; }
            }
        }
#pragma unroll
        for (int off = 16; off; off >>= 1) {
            float od = __shfl_down_sync(0xffffffffu, best, off);
            int   oi = __shfl_down_sync(0xffffffffu, bi, off);
            if (od < best || (od == best && oi < bi)) { best = od; bi = oi; }
        }
        if (lane == 0) { rd[wid] = best; ri[wid] = bi; }
        __syncthreads();
        if (wid == 0) {
            best = rd[lane]; bi = ri[lane];
#pragma unroll
            for (int off = 16; off; off >>= 1) {
                float od = __shfl_down_sync(0xffffffffu, best, off);
                int   oi = __shfl_down_sync(0xffffffffu, bi, off);
                if (od < best || (od == best && oi < bi)) { best = od; bi = oi; }
            }
            if (lane == 0) { topi[k] = bi; topd[k] = best; }
        }
        __syncthreads();
        if (k == 0) {
            // bmu1 known: launch edge/age row loads (latency hidden by passes 1..7)
            int b1l = topi[0];
            const float* er = edges + (size_t)b1l * N_CELLS;
            const float* ar = eages + (size_t)b1l * N_CELLS;
#pragma unroll
            for (int u = 0; u < 8; ++u) {
                pe[u] = er[tid + u * 1024];
                pa[u] = ar[tid + u * 1024];
            }
        }
    }

    // ---- constants + softmax weights ----
    if (tid == 0) {
        int step = stepp[0];
        s_step = step;
        float ew = 0.3f * expf(-(float)step / 200.0f);
        if (ew < 0.05f) ew = 0.05f;
        s_epsw = ew;
        s_epsn = ew * 0.01f;
        s_b1 = topi[0];
        s_b2 = topi[1];
        float z = 0.f;
        for (int k = 0; k < TOPK; ++k) {
            float e = expf(-(topd[k] - topd[0]));
            w8[k] = e;
            z += e;
        }
        float inv = 1.0f / z;
        for (int k = 0; k < TOPK; ++k) w8[k] *= inv;
    }
    __syncthreads();
    const int b1 = s_b1, b2 = s_b2;
    const float epsw = s_epsw, epsn = s_epsn;

    // ---- neighbor mask from prefetched edges/ages row b1 ----
#pragma unroll
    for (int u = 0; u < 8; ++u) {
        int j = tid + u * 1024;
        float ev = pe[u];
        float ag = pa[u];
        if (j == b2) { ev = 1.f; ag = 0.f; }
        ag += 1.f;
        if (j == b1) ag += 1.f;      // row add + column add hit the diagonal
        bool nm = (ag <= 50.f) && (ev > 0.f);
        nmask[j] = nm ? 1 : 0;
        if (nm && j != b1 && j != b2) {
            int f = j >> 10;
            atomicAdd(&cnt[f], 1);
            const float* pr = proto + (size_t)j * HID;
            for (int d = 0; d < HID; ++d) atomicAdd(&dsum[f][d], pr[d]);
        }
    }
    __syncthreads();

    // ---- bmu1 / bmu2 rows after all pre-sync updates ----
    if (tid < HID) {
        int d = tid;
        float s = ssig[d];
        float p1 = proto[(size_t)b1 * HID + d];
        float v1 = p1 + epsw * (s - p1);
        if (nmask[b1]) v1 = v1 + epsn * (s - v1);
        p1s[d] = v1;
        float p2 = proto[(size_t)b2 * HID + d];
        float v2 = p2 + epsn * (s - p2);
        if (nmask[b2]) v2 = v2 + epsn * (s - v2);
        p2s[d] = v2;
    }
    __syncthreads();

    // ---- faction means (original sums + exact deltas of updated rows) ----
    {
        int f = tid >> 7, d = tid & 127;   // blockDim == 1024 covers all (f,d)
        float adj = epsn * (ssig[d] * (float)cnt[f] - dsum[f][d]);
        if ((b1 >> 10) == f) adj += p1s[d] - proto[(size_t)b1 * HID + d];
        if ((b2 >> 10) == f) adj += p2s[d] - proto[(size_t)b2 * HID + d];
        fmean[f][d] = (g_fsum[f * HID + d] + adj) * (1.0f / FS);
    }
    __syncthreads();
    if (tid < HID) {
        float g = 0.f;
#pragma unroll
        for (int f = 0; f < NFAC; ++f) g += fmean[f][tid];
        gmean[tid] = g * (1.0f / NFAC);
    }
    __syncthreads();

    const bool debate = s_step > 5;

    // ---- winner row after faction sync / debate ----
    if (tid < HID) {
        int f = b1 >> 10, p = b1 & (FS - 1);
        float v = 0.85f * p1s[tid] + 0.15f * fmean[f][tid];
        if (debate && p < 256) v = 0.85f * v + 0.15f * gmean[tid];
        win[tid] = v;
    }
    __syncthreads();

    // ---- expert hidden layers (tids 0-127) + weighted combine (tids 128-255)
    if (tid < HID) {
        float a1 = ea_b1[tid], a2 = eg_b1[tid];
        const float* w1 = ea_w1 + tid * HID;
        const float* w2 = eg_w1 + tid * HID;
        for (int d = 0; d < HID; ++d) {
            float wv = win[d];
            a1 += wv * w1[d];
            a2 += wv * w2[d];
        }
        h1[tid] = a1 > 0.f ? a1 : 0.f;
        h2[tid] = a2 > 0.f ? a2 : 0.f;
    } else if (tid < 256) {
        int d = tid - 128;
        float acc = 0.f;
#pragma unroll
        for (int k = 0; k < TOPK; ++k) {
            int i = topi[k];
            float pv;
            if (k == 0)      pv = p1s[d];
            else if (k == 1) pv = p2s[d];
            else {
                pv = proto[(size_t)i * HID + d];
                if (nmask[i]) pv = pv + epsn * (ssig[d] - pv);
            }
            int f = i >> 10, p = i & (FS - 1);
            float v = 0.85f * pv + 0.15f * fmean[f][d];
            if (debate && p < 256) v = 0.85f * v + 0.15f * gmean[d];
            acc += w8[k] * v;
        }
        comb[d] = acc;
    }
    __syncthreads();

    // ---- expert outputs + tension (tids 0-63); final output (tids 64-127)
    if (tid < OUT_DIM) {
        float a = ea_b2[tid], g = eg_b2[tid];
        const float* wa = ea_w2 + tid * HID;
        const float* wg = eg_w2 + tid * HID;
        for (int d = 0; d < HID; ++d) {
            a += h1[d] * wa[d];
            g += h2[d] * wg[d];
        }
        float diff = a - g;
        diff *= diff;
#pragma unroll
        for (int off = 16; off; off >>= 1)
            diff += __shfl_down_sync(0xffffffffu, diff, off);
        if (lane == 0) rd[wid] = diff;          // wid 0, 1
    } else if (tid < 128) {
        int o = tid - 64;
        float acc = out_b[o];
        const float* wo = out_w + o * HID;
        for (int d = 0; d < HID; ++d) acc += comb[d] * wo[d];
        out[o] = acc;
    }
    __syncthreads();
    if (tid == 0) out[OUT_DIM] = (rd[0] + rd[1]) * (1.0f / 64.0f);
}

// ---------------------------------------------------------------------------
extern "C" void kernel_launch(void* const* d_in, const int* in_sizes, int n_in,
                              void* d_out, int out_size) {
    const float* x      = (const float*)d_in[0];
    const int*   step   = (const int*)  d_in[1];
    const float* proto  = (const float*)d_in[2];
    const float* edges  = (const float*)d_in[3];
    const float* eages  = (const float*)d_in[4];
    const float* in_w   = (const float*)d_in[5];
    const float* in_b   = (const float*)d_in[6];
    const float* out_w  = (const float*)d_in[7];
    const float* out_b  = (const float*)d_in[8];
    const float* ea_w1  = (const float*)d_in[9];
    const float* ea_b1  = (const float*)d_in[10];
    const float* ea_w2  = (const float*)d_in[11];
    const float* ea_b2  = (const float*)d_in[12];
    const float* eg_w1  = (const float*)d_in[13];
    const float* eg_b1  = (const float*)d_in[14];
    const float* eg_w2  = (const float*)d_in[15];
    const float* eg_b2  = (const float*)d_in[16];
    float* out = (float*)d_out;

    k_signal<<<1, 256>>>(x, in_w, in_b);
    k_dists<<<1024, 256>>>(proto);
    k_main<<<1, 1024>>>(proto, edges, eages, step,
                        out_w, out_b,
                        ea_w1, ea_b1, ea_w2, ea_b2,
                        eg_w1, eg_b1, eg_w2, eg_b2,
                        out);
}

// round 9
// speedup vs baseline: 2.9430x; 2.9430x over previous
#include <cuda_runtime.h>
#include <math.h>

#define N_CELLS 8192
#define HID 128
#define IN_DIM 64
#define OUT_DIM 64
#define NFAC 8
#define FS 1024
#define TOPK 8
#define NCAP 4096
#define FMAX 3.402823466e38f

__device__ __align__(16) float g_dists[N_CELLS];
__device__ __align__(16) float g_fpart[128 * HID];   // per-block faction partial sums

// ---------------------------------------------------------------------------
// K1: signal (recomputed per block) + per-row squared distances + per-block
//     prototype partial sums. 128 blocks x 256 threads, 64 rows per block,
//     warp-per-row, 8 passes. Block b belongs to faction b>>4.
// ---------------------------------------------------------------------------
__global__ void __launch_bounds__(256)
k_dists(const float* __restrict__ x,
        const float* __restrict__ in_w,
        const float* __restrict__ in_b,
        const float* __restrict__ proto) {
    __shared__ __align__(16) float ssig[HID];
    __shared__ float sfs_w[8][HID];
    int tid = threadIdx.x, wid = tid >> 5, lane = tid & 31;

    if (tid < HID) {
        float acc = in_b[tid];
        const float4* w4 = (const float4*)(in_w + tid * IN_DIM);
        const float4* x4 = (const float4*)x;
#pragma unroll
        for (int i = 0; i < IN_DIM / 4; ++i) {
            float4 wv = w4[i], xv = x4[i];
            acc += wv.x * xv.x + wv.y * xv.y + wv.z * xv.z + wv.w * xv.w;
        }
        ssig[tid] = acc;
    }
    __syncthreads();

    int d0 = lane * 4;
    float s0 = ssig[d0], s1 = ssig[d0 + 1], s2 = ssig[d0 + 2], s3 = ssig[d0 + 3];
    float ax = 0.f, ay = 0.f, az = 0.f, aw = 0.f;
    int row0 = blockIdx.x * 64;
#pragma unroll
    for (int p = 0; p < 8; ++p) {
        int row = row0 + p * 8 + wid;
        float4 a = ((const float4*)(proto + (size_t)row * HID))[lane];
        ax += a.x; ay += a.y; az += a.z; aw += a.w;
        float dx = a.x - s0, dy = a.y - s1, dz = a.z - s2, dw = a.w - s3;
        float s = dx * dx + dy * dy + dz * dz + dw * dw;
#pragma unroll
        for (int off = 16; off; off >>= 1) s += __shfl_down_sync(0xffffffffu, s, off);
        if (lane == 0) g_dists[row] = s;
    }
    ((float4*)&sfs_w[wid][d0])[0] = make_float4(ax, ay, az, aw);
    __syncthreads();
    if (tid < HID) {
        float t = 0.f;
#pragma unroll
        for (int w = 0; w < 8; ++w) t += sfs_w[w][tid];
        g_fpart[blockIdx.x * HID + tid] = t;
    }
}

// ---------------------------------------------------------------------------
// K2: everything else in one block of 1024 threads
// ---------------------------------------------------------------------------
__global__ void __launch_bounds__(1024, 1)
k_main(const float* __restrict__ x,
       const float* __restrict__ in_w,
       const float* __restrict__ in_b,
       const float* __restrict__ proto,
       const float* __restrict__ edges,
       const float* __restrict__ eages,
       const int* __restrict__ stepp,
       const float* __restrict__ out_w, const float* __restrict__ out_b,
       const float* __restrict__ ea_w1, const float* __restrict__ ea_b1,
       const float* __restrict__ ea_w2, const float* __restrict__ ea_b2,
       const float* __restrict__ eg_w1, const float* __restrict__ eg_b1,
       const float* __restrict__ eg_w2, const float* __restrict__ eg_b2,
       float* __restrict__ out) {
    __shared__ __align__(16) float ssig[HID];
    __shared__ float fsum[NFAC][HID];
    __shared__ float dsum[NFAC][HID];
    __shared__ float fmean[NFAC][HID];
    __shared__ __align__(16) float p1s[HID], p2s[HID], p1o[HID], p2o[HID];
    __shared__ __align__(16) float win[HID];
    __shared__ __align__(16) float comb[HID];
    __shared__ __align__(16) float h1[HID], h2[HID];
    __shared__ float candd[256];
    __shared__ int   candi[256];
    __shared__ int   topi[TOPK];
    __shared__ float topd[TOPK];
    __shared__ float w8raw[TOPK];
    __shared__ float rd[2];
    __shared__ unsigned char nmask[N_CELLS];
    __shared__ int nlist[NCAP];
    __shared__ int cnt[NFAC];
    __shared__ int ncount;

    int tid = threadIdx.x;
    int lane = tid & 31, wid = tid >> 5;
    int ff = tid >> 7, dd = tid & 127;

    // per-thread constants
    int step = stepp[0];
    float epsw = 0.3f * expf(-(float)step / 200.0f);
    if (epsw < 0.05f) epsw = 0.05f;
    float epsn = epsw * 0.01f;
    bool debate = step > 5;

    // ---- S0: signal, faction-sum reduction, zeroing, warp-local top-8 ----
    if (tid < HID) {
        float acc = in_b[tid];
        const float4* w4 = (const float4*)(in_w + tid * IN_DIM);
        const float4* x4 = (const float4*)x;
#pragma unroll
        for (int i = 0; i < IN_DIM / 4; ++i) {
            float4 wv = w4[i], xv = x4[i];
            acc += wv.x * xv.x + wv.y * xv.y + wv.z * xv.z + wv.w * xv.w;
        }
        ssig[tid] = acc;
    }
    {
        float t = 0.f;
#pragma unroll
        for (int b = 0; b < 16; ++b) t += g_fpart[(ff * 16 + b) * HID + dd];
        fsum[ff][dd] = t;
        dsum[ff][dd] = 0.f;
    }
    if (tid < NFAC) cnt[tid] = 0;
    if (tid == 0) ncount = 0;

    // stage-1: each warp's top-8 over its 256 cells (register-resident)
    {
        int base = wid * 256 + lane * 8;
        float dv[8];
        const float4* dp = (const float4*)(g_dists + base);
        float4 a = dp[0], b = dp[1];
        dv[0] = a.x; dv[1] = a.y; dv[2] = a.z; dv[3] = a.w;
        dv[4] = b.x; dv[5] = b.y; dv[6] = b.z; dv[7] = b.w;
#pragma unroll
        for (int k = 0; k < TOPK; ++k) {
            float lb = dv[0]; int li = 0;
#pragma unroll
            for (int i = 1; i < 8; ++i)
                if (dv[i] < lb) { lb = dv[i]; li = i; }
            int gi = base + li;
            float wd = lb; int wi = gi;
#pragma unroll
            for (int off = 16; off; off >>= 1) {
                float od = __shfl_xor_sync(0xffffffffu, wd, off);
                int   oi = __shfl_xor_sync(0xffffffffu, wi, off);
                if (od < wd || (od == wd && oi < wi)) { wd = od; wi = oi; }
            }
            if (wi == gi) dv[li] = FMAX;
            if (lane == k) { candd[wid * 8 + k] = wd; candi[wid * 8 + k] = wi; }
        }
    }
    __syncthreads();   // BAR1

    // stage-2: warp 0 selects global top-8 from 256 candidates
    if (wid == 0) {
        float dv[8]; int iv[8];
#pragma unroll
        for (int i = 0; i < 8; ++i) { dv[i] = candd[lane * 8 + i]; iv[i] = candi[lane * 8 + i]; }
#pragma unroll
        for (int k = 0; k < TOPK; ++k) {
            float lb = dv[0]; int li = 0;
#pragma unroll
            for (int i = 1; i < 8; ++i)
                if (dv[i] < lb || (dv[i] == lb && iv[i] < iv[li])) { lb = dv[i]; li = i; }
            float wd = lb; int wi = iv[li];
#pragma unroll
            for (int off = 16; off; off >>= 1) {
                float od = __shfl_xor_sync(0xffffffffu, wd, off);
                int   oi = __shfl_xor_sync(0xffffffffu, wi, off);
                if (od < wd || (od == wd && oi < wi)) { wd = od; wi = oi; }
            }
            if (wi == iv[li]) dv[li] = FMAX;
            if (lane == k) { topd[k] = wd; topi[k] = wi; }
        }
    }
    __syncthreads();   // BAR2

    const int b1 = topi[0], b2 = topi[1];

    // ---- edge/age row scan (8 elems/thread, float4) + neighbor list ----
    {
        int j0 = tid * 8;
        const float4* er = (const float4*)(edges + (size_t)b1 * N_CELLS + j0);
        const float4* ar = (const float4*)(eages + (size_t)b1 * N_CELLS + j0);
        float4 e0 = er[0], e1 = er[1], a0 = ar[0], a1v = ar[1];
        float ev[8] = { e0.x, e0.y, e0.z, e0.w, e1.x, e1.y, e1.z, e1.w };
        float ag[8] = { a0.x, a0.y, a0.z, a0.w, a1v.x, a1v.y, a1v.z, a1v.w };
#pragma unroll
        for (int i = 0; i < 8; ++i) {
            int j = j0 + i;
            float e = ev[i], a = ag[i];
            if (j == b2) { e = 1.f; a = 0.f; }
            a += 1.f;
            if (j == b1) a += 1.f;     // row-add + col-add both hit diagonal
            bool nm = (a <= 50.f) && (e > 0.f);
            nmask[j] = nm ? 1 : 0;
            if (nm && j != b1 && j != b2) {
                atomicAdd(&cnt[j >> 10], 1);
                int pos = atomicAdd(&ncount, 1);
                if (pos < NCAP) nlist[pos] = j;
                else {  // overflow fallback: direct accumulation (correct, slow)
                    const float* pr = proto + (size_t)j * HID;
                    for (int d = 0; d < HID; ++d) atomicAdd(&dsum[j >> 10][d], pr[d]);
                }
            }
        }
    }
    if (tid < TOPK) w8raw[tid] = expf(-(topd[tid] - topd[0]));
    __syncthreads();   // BAR3

    // ---- cooperative dsum accumulation + bmu row updates ----
    {
        int n = ncount < NCAP ? ncount : NCAP;
        for (int e = ff; e < n; e += NFAC) {
            int j = nlist[e];
            atomicAdd(&dsum[j >> 10][dd], proto[(size_t)j * HID + dd]);
        }
    }
    if (tid < HID) {
        int d = tid;
        float s = ssig[d];
        float p1 = proto[(size_t)b1 * HID + d];
        p1o[d] = p1;
        float v1 = p1 + epsw * (s - p1);
        if (nmask[b1]) v1 = v1 + epsn * (s - v1);
        p1s[d] = v1;
        float p2 = proto[(size_t)b2 * HID + d];
        p2o[d] = p2;
        float v2 = p2 + epsn * (s - p2);
        if (nmask[b2]) v2 = v2 + epsn * (s - v2);
        p2s[d] = v2;
    }
    __syncthreads();   // BAR4

    // ---- faction means: original sums + exact deltas ----
    {
        float adj = epsn * (ssig[dd] * (float)cnt[ff] - dsum[ff][dd]);
        if ((b1 >> 10) == ff) adj += p1s[dd] - p1o[dd];
        if ((b2 >> 10) == ff) adj += p2s[dd] - p2o[dd];
        fmean[ff][dd] = (fsum[ff][dd] + adj) * (1.0f / FS);
    }
    __syncthreads();   // BAR5

    // ---- winner row (tids 0-127) + weighted combine (tids 128-255) ----
    if (tid < HID) {
        float g = 0.f;
#pragma unroll
        for (int f = 0; f < NFAC; ++f) g += fmean[f][tid];
        g *= (1.0f / NFAC);
        int f = b1 >> 10, p = b1 & (FS - 1);
        float v = 0.85f * p1s[tid] + 0.15f * fmean[f][tid];
        if (debate && p < 256) v = 0.85f * v + 0.15f * g;
        win[tid] = v;
    } else if (tid < 256) {
        int d = tid - 128;
        float g = 0.f;
#pragma unroll
        for (int f = 0; f < NFAC; ++f) g += fmean[f][d];
        g *= (1.0f / NFAC);
        float wsum = 0.f;
#pragma unroll
        for (int k = 0; k < TOPK; ++k) wsum += w8raw[k];
        float inv = 1.0f / wsum;
        float acc = 0.f;
#pragma unroll
        for (int k = 0; k < TOPK; ++k) {
            int i = topi[k];
            float pv;
            if (k == 0)      pv = p1s[d];
            else if (k == 1) pv = p2s[d];
            else {
                pv = proto[(size_t)i * HID + d];
                if (nmask[i]) pv = pv + epsn * (ssig[d] - pv);
            }
            float v = 0.85f * pv + 0.15f * fmean[i >> 10][d];
            if (debate && (i & (FS - 1)) < 256) v = 0.85f * v + 0.15f * g;
            acc += w8raw[k] * v;
        }
        comb[d] = acc * inv;
    }
    __syncthreads();   // BAR6

    // ---- expert hidden layers (float4 weight loads) ----
    if (tid < HID) {
        const float4* w1 = (const float4*)(ea_w1 + tid * HID);
        const float4* w2 = (const float4*)(eg_w1 + tid * HID);
        const float4* wv4 = (const float4*)win;
        float a0 = 0.f, a1 = 0.f, a2 = 0.f, a3 = 0.f;
        float g0 = 0.f, g1 = 0.f, g2 = 0.f, g3 = 0.f;
#pragma unroll
        for (int i = 0; i < HID / 4; ++i) {
            float4 wa = w1[i], wg = w2[i], hv = wv4[i];
            a0 += wa.x * hv.x; a1 += wa.y * hv.y; a2 += wa.z * hv.z; a3 += wa.w * hv.w;
            g0 += wg.x * hv.x; g1 += wg.y * hv.y; g2 += wg.z * hv.z; g3 += wg.w * hv.w;
        }
        float a = ea_b1[tid] + (a0 + a1) + (a2 + a3);
        float gg = eg_b1[tid] + (g0 + g1) + (g2 + g3);
        h1[tid] = a > 0.f ? a : 0.f;
        h2[tid] = gg > 0.f ? gg : 0.f;
    }
    __syncthreads();   // BAR7

    // ---- expert outputs + tension (tids 0-63); final output (tids 64-127) --
    if (tid < OUT_DIM) {
        const float4* wa = (const float4*)(ea_w2 + tid * HID);
        const float4* wg = (const float4*)(eg_w2 + tid * HID);
        const float4* h14 = (const float4*)h1;
        const float4* h24 = (const float4*)h2;
        float a = ea_b2[tid], g = eg_b2[tid];
#pragma unroll
        for (int i = 0; i < HID / 4; ++i) {
            float4 va = wa[i], vg = wg[i], v1 = h14[i], v2 = h24[i];
            a += va.x * v1.x + va.y * v1.y + va.z * v1.z + va.w * v1.w;
            g += vg.x * v2.x + vg.y * v2.y + vg.z * v2.z + vg.w * v2.w;
        }
        float diff = a - g;
        diff *= diff;
#pragma unroll
        for (int off = 16; off; off >>= 1)
            diff += __shfl_down_sync(0xffffffffu, diff, off);
        if (lane == 0) rd[wid] = diff;           // wid 0, 1
    } else if (tid < 128) {
        int o = tid - 64;
        const float4* wo = (const float4*)(out_w + o * HID);
        const float4* c4 = (const float4*)comb;
        float acc = out_b[o];
#pragma unroll
        for (int i = 0; i < HID / 4; ++i) {
            float4 wv = wo[i], cv = c4[i];
            acc += wv.x * cv.x + wv.y * cv.y + wv.z * cv.z + wv.w * cv.w;
        }
        out[o] = acc;
    }
    __syncthreads();   // BAR8
    if (tid == 0) out[OUT_DIM] = (rd[0] + rd[1]) * (1.0f / 64.0f);
}

// ---------------------------------------------------------------------------
extern "C" void kernel_launch(void* const* d_in, const int* in_sizes, int n_in,
                              void* d_out, int out_size) {
    const float* x      = (const float*)d_in[0];
    const int*   step   = (const int*)  d_in[1];
    const float* proto  = (const float*)d_in[2];
    const float* edges  = (const float*)d_in[3];
    const float* eages  = (const float*)d_in[4];
    const float* in_w   = (const float*)d_in[5];
    const float* in_b   = (const float*)d_in[6];
    const float* out_w  = (const float*)d_in[7];
    const float* out_b  = (const float*)d_in[8];
    const float* ea_w1  = (const float*)d_in[9];
    const float* ea_b1  = (const float*)d_in[10];
    const float* ea_w2  = (const float*)d_in[11];
    const float* ea_b2  = (const float*)d_in[12];
    const float* eg_w1  = (const float*)d_in[13];
    const float* eg_b1  = (const float*)d_in[14];
    const float* eg_w2  = (const float*)d_in[15];
    const float* eg_b2  = (const float*)d_in[16];
    float* out = (float*)d_out;

    k_dists<<<128, 256>>>(x, in_w, in_b, proto);
    k_main<<<1, 1024>>>(x, in_w, in_b, proto, edges, eages, step,
                        out_w, out_b,
                        ea_w1, ea_b1, ea_w2, ea_b2,
                        eg_w1, eg_b1, eg_w2, eg_b2,
                        out);
}